// round 3
// baseline (speedup 1.0000x reference)
#include <cuda_runtime.h>

#define BATCH    256
#define IN_CAPS  1152
#define NUM_CAPS 10
#define DIM_VEC  16
#define ITILE    8
#define NBLK_I   (IN_CAPS / ITILE)      // 144
#define B_PER_BLK 24                    // 8 warps x 3 b
#define NBLK_B   11                     // ceil(256/24)
#define NTH      256
#define EPS 1e-7f

// ws: float [ii][e][c][20] (d=0..15 + pad4)  -> 8*8*10*20 floats = 51200 B
// xs: ull   [24][66]  (x duplicated in both halves, padded row)  = 12672 B
#define WS_F   (ITILE * 8 * NUM_CAPS * 20)
#define XS_U   (B_PER_BLK * 66)
#define SMEM_BYTES (WS_F * 4 + XS_U * 8)

__device__ float g_sbuf[3][BATCH * NUM_CAPS * DIM_VEC];       // zero-init; final re-zeros
__device__ float g_blog[IN_CAPS * BATCH * NUM_CAPS];          // [i][b][c]

using ull = unsigned long long;
__device__ __forceinline__ ull pack2(float lo, float hi) {
    ull r; asm("mov.b64 %0,{%1,%2};" : "=l"(r) : "f"(lo), "f"(hi)); return r;
}
__device__ __forceinline__ void unpack2(ull v, float& lo, float& hi) {
    asm("mov.b64 {%0,%1},%2;" : "=f"(lo), "=f"(hi) : "l"(v));
}
__device__ __forceinline__ ull ffma2(ull a, ull b, ull c) {
    ull d; asm("fma.rn.f32x2 %0,%1,%2,%3;" : "=l"(d) : "l"(a), "l"(b), "l"(c)); return d;
}

// PASS 0: coef = softmax(bias); s0 += coef*u_hat
// PASS 1: v1=squash(s0); b1 = uh.v1 + 2*bias (store); s1 += softmax(b1)*u_hat
// PASS 2: v2=squash(s1); b2 = uh.v2 + b1 + bias;      s2 += softmax(b2)*u_hat
template <int PASS>
__global__ void __launch_bounds__(NTH)
pass_kernel(const float* __restrict__ x,     // [256,1152,8]
            const float* __restrict__ W,     // [1152,10,16,8]
            const float* __restrict__ bias)  // [1152,10]
{
    extern __shared__ __align__(16) float sh[];
    float* ws = sh;                          // W tile
    ull*   xs = (ull*)(sh + WS_F);           // x tile (dup-packed)

    const int tid  = threadIdx.x;
    const int wrp  = tid >> 5;
    const int lane = tid & 31;
    const int gg   = lane / 10;              // 0..2 (3 = idle lane 30/31)
    const int g    = (gg < 3) ? gg : 2;
    const int lin  = lane % 10;              // capsule index c
    const int c    = lin;
    const int i0   = blockIdx.x * ITILE;
    const int b0   = blockIdx.y * B_PER_BLK;
    const int b_raw = b0 + wrp * 3 + g;
    const bool active = (gg < 3) && (b_raw < BATCH);
    const int b    = active ? b_raw : (BATCH - 1);
    const int lb   = wrp * 3 + g;

    // ---- Stage W tile: global [i][c][d][e] -> shared [ii][e][c][d(pad20)]
    {
        const float4* Wg = (const float4*)(W + (size_t)i0 * NUM_CAPS * DIM_VEC * 8);
        #pragma unroll 2
        for (int k = tid; k < ITILE * NUM_CAPS * DIM_VEC * 2; k += NTH) {
            float4 w4 = Wg[k];                       // coalesced LDG.128
            int ii = k / (NUM_CAPS * DIM_VEC * 2);   // /320
            int cc = (k >> 5) % NUM_CAPS;
            int d  = (k >> 1) & 15;
            int eh = k & 1;
            float* dst = ws + ii * 1600 + cc * 20 + d + (eh * 4) * 200;
            dst[0 * 200] = w4.x;
            dst[1 * 200] = w4.y;
            dst[2 * 200] = w4.z;
            dst[3 * 200] = w4.w;
        }
    }
    // ---- Stage x tile dup-packed: xs[lb][j] = (x, x)
    for (int t = tid; t < B_PER_BLK * ITILE * 8; t += NTH) {
        int xlb = t >> 6;                            // /64
        int j   = t & 63;
        int bb  = b0 + xlb; if (bb >= BATCH) bb = BATCH - 1;
        float v = x[(size_t)bb * (IN_CAPS * 8) + i0 * 8 + j];
        xs[xlb * 66 + j] = pack2(v, v);
    }

    // ---- v = squash(s_prev) for this (b,c); loop-invariant
    ull vv2[8];
    if (PASS > 0) {
        const float4* sp = (const float4*)(g_sbuf[PASS - 1] + (b * NUM_CAPS + c) * DIM_VEC);
        float4 s4[4]; float sq = 0.f;
        #pragma unroll
        for (int q = 0; q < 4; q++) {
            s4[q] = sp[q];
            sq = fmaf(s4[q].x, s4[q].x, sq); sq = fmaf(s4[q].y, s4[q].y, sq);
            sq = fmaf(s4[q].z, s4[q].z, sq); sq = fmaf(s4[q].w, s4[q].w, sq);
        }
        float scale = sq / (1.f + sq) * rsqrtf(sq + EPS);
        #pragma unroll
        for (int q = 0; q < 4; q++) {
            vv2[2 * q]     = pack2(scale * s4[q].x, scale * s4[q].y);
            vv2[2 * q + 1] = pack2(scale * s4[q].z, scale * s4[q].w);
        }
    }
    __syncthreads();   // staging complete (only barrier in the kernel)

    // shfl source lanes for the 10-wide softmax group (ring offsets 1..9)
    int srcs[9];
    #pragma unroll
    for (int j = 1; j <= 9; j++) {
        int l2 = lin + j; if (l2 >= 10) l2 -= 10;
        srcs[j - 1] = g * 10 + l2;
    }

    ull sacc2[8];
    #pragma unroll
    for (int p = 0; p < 8; p++) sacc2[p] = 0ull;

    #pragma unroll 2
    for (int ii = 0; ii < ITILE; ii++) {
        const int i = i0 + ii;
        const float bs = __ldg(&bias[i * NUM_CAPS + c]);        // 30 consecutive floats / warp
        float bprev = 0.f;
        if (PASS == 2) bprev = g_blog[(size_t)i * (BATCH * NUM_CAPS) + b * NUM_CAPS + c];

        ull x2[8];
        #pragma unroll
        for (int e = 0; e < 8; e++) x2[e] = xs[lb * 66 + ii * 8 + e];   // conflict-free bcast

        // u_hat[c, 0..15] as 8 f32x2 : 32 LDS.128 + 64 FFMA2
        ull uh2[8];
        #pragma unroll
        for (int p = 0; p < 8; p++) uh2[p] = 0ull;
        #pragma unroll
        for (int e = 0; e < 8; e++) {
            const ulonglong2* wp = (const ulonglong2*)(ws + ii * 1600 + e * 200 + c * 20);
            #pragma unroll
            for (int q = 0; q < 4; q++) {
                ulonglong2 wv = wp[q];
                uh2[2 * q]     = ffma2(wv.x, x2[e], uh2[2 * q]);
                uh2[2 * q + 1] = ffma2(wv.y, x2[e], uh2[2 * q + 1]);
            }
        }

        float bnew;
        if (PASS == 0) {
            bnew = bs;
        } else {
            ull ag = 0ull;
            #pragma unroll
            for (int p = 0; p < 8; p++) ag = ffma2(uh2[p], vv2[p], ag);
            float alo, ahi; unpack2(ag, alo, ahi);
            float agr = alo + ahi;
            if (PASS == 1) {
                bnew = agr + 2.f * bs;
                if (active) g_blog[(size_t)i * (BATCH * NUM_CAPS) + b * NUM_CAPS + c] = bnew;
            } else {
                bnew = agr + bprev + bs;
            }
        }

        // warp-local softmax over the 10 capsules of this (b,i): no barriers
        float m = bnew;
        #pragma unroll
        for (int j = 0; j < 9; j++) m = fmaxf(m, __shfl_sync(0xffffffffu, bnew, srcs[j]));
        float ex = __expf(bnew - m);
        float den = ex;
        #pragma unroll
        for (int j = 0; j < 9; j++) den += __shfl_sync(0xffffffffu, ex, srcs[j]);
        float coef = __fdividef(ex, den);
        ull cf = pack2(coef, coef);
        #pragma unroll
        for (int p = 0; p < 8; p++) sacc2[p] = ffma2(cf, uh2[p], sacc2[p]);
    }

    // s[b,c,:] partial over this block's 8 i's -> 4 vectored reductions
    if (active) {
        float* sp = g_sbuf[PASS] + (b * NUM_CAPS + c) * DIM_VEC;
        #pragma unroll
        for (int q = 0; q < 4; q++) {
            float a0, a1, a2, a3;
            unpack2(sacc2[2 * q], a0, a1);
            unpack2(sacc2[2 * q + 1], a2, a3);
            asm volatile("red.global.add.v4.f32 [%0], {%1,%2,%3,%4};"
                         :: "l"(sp + 4 * q), "f"(a0), "f"(a1), "f"(a2), "f"(a3)
                         : "memory");
        }
    }
}

// out = squash(s2); re-zero all scratch for graph-replay determinism
__global__ void final_kernel(float* __restrict__ out)
{
    int t = blockIdx.x * blockDim.x + threadIdx.x;       // 40960 threads
    if (t < BATCH * NUM_CAPS) {                          // one (b,c) row each
        float4* sp = (float4*)(g_sbuf[2] + t * DIM_VEC);
        float4 s4[4]; float sq = 0.f;
        #pragma unroll
        for (int q = 0; q < 4; q++) {
            s4[q] = sp[q];
            sq = fmaf(s4[q].x, s4[q].x, sq); sq = fmaf(s4[q].y, s4[q].y, sq);
            sq = fmaf(s4[q].z, s4[q].z, sq); sq = fmaf(s4[q].w, s4[q].w, sq);
        }
        float scale = sq / (1.f + sq) * rsqrtf(sq + EPS);
        float4* dst = (float4*)(out + t * DIM_VEC);
        float4 z = make_float4(0.f, 0.f, 0.f, 0.f);
        #pragma unroll
        for (int q = 0; q < 4; q++) {
            float4 o; o.x = scale * s4[q].x; o.y = scale * s4[q].y;
                      o.z = scale * s4[q].z; o.w = scale * s4[q].w;
            dst[q] = o;
            sp[q] = z;                                    // zero s2 (own row: no race)
        }
    }
    // zero s0 / s1 (one float each per thread)
    if (t < BATCH * NUM_CAPS * DIM_VEC) {
        g_sbuf[0][t] = 0.f;
        g_sbuf[1][t] = 0.f;
    }
}

extern "C" void kernel_launch(void* const* d_in, const int* in_sizes, int n_in,
                              void* d_out, int out_size)
{
    const float* x = nullptr; const float* W = nullptr; const float* bias = nullptr;
    for (int k = 0; k < n_in; k++) {
        if (in_sizes[k] == BATCH * IN_CAPS * 8)                    x    = (const float*)d_in[k];
        else if (in_sizes[k] == IN_CAPS * NUM_CAPS * DIM_VEC * 8)  W    = (const float*)d_in[k];
        else if (in_sizes[k] == IN_CAPS * NUM_CAPS)                bias = (const float*)d_in[k];
    }
    float* out = (float*)d_out;

    static bool attr_set = false;
    if (!attr_set) {
        cudaFuncSetAttribute(pass_kernel<0>, cudaFuncAttributeMaxDynamicSharedMemorySize, SMEM_BYTES);
        cudaFuncSetAttribute(pass_kernel<1>, cudaFuncAttributeMaxDynamicSharedMemorySize, SMEM_BYTES);
        cudaFuncSetAttribute(pass_kernel<2>, cudaFuncAttributeMaxDynamicSharedMemorySize, SMEM_BYTES);
        attr_set = true;
    }

    dim3 grd(NBLK_I, NBLK_B);
    pass_kernel<0><<<grd, NTH, SMEM_BYTES>>>(x, W, bias);
    pass_kernel<1><<<grd, NTH, SMEM_BYTES>>>(x, W, bias);
    pass_kernel<2><<<grd, NTH, SMEM_BYTES>>>(x, W, bias);
    final_kernel<<<(BATCH * NUM_CAPS * DIM_VEC + 255) / 256, 256>>>(out);
}

// round 4
// speedup vs baseline: 2.3252x; 2.3252x over previous
#include <cuda_runtime.h>

#define BATCH    256
#define IN_CAPS  1152
#define NUM_CAPS 10
#define DIM_VEC  16
#define ITILE    16
#define NBLK_I   (IN_CAPS / ITILE)    // 72
#define B_TILE   32
#define NBLK_B   (BATCH / B_TILE)     // 8
#define NTH      (B_TILE * NUM_CAPS)  // 320
#define EPS 1e-7f

// Shared carve-up (floats)
#define WS_F  (ITILE * NUM_CAPS * 8 * DIM_VEC)   // 20480 floats (80 KB): [ii][c][e][d16]
#define XS_F  (ITILE * 8 * 33)                   // 4224 floats (16.5 KB): [j][b(pad33)]
#define EX_F  (2 * B_TILE * 11)                  // 704: double-buffered exp exchange
#define SMEM_BYTES ((WS_F + XS_F + EX_F) * 4)    // 101632 B

__device__ float g_sbuf[3][BATCH * NUM_CAPS * DIM_VEC];   // zero-init; final re-zeros
__device__ float g_blog[IN_CAPS * NUM_CAPS * BATCH];      // [i][c][b] : coalesced over b

using ull = unsigned long long;
__device__ __forceinline__ ull pack2(float lo, float hi) {
    ull r; asm("mov.b64 %0,{%1,%2};" : "=l"(r) : "f"(lo), "f"(hi)); return r;
}
__device__ __forceinline__ void unpack2(ull v, float& lo, float& hi) {
    asm("mov.b64 {%0,%1},%2;" : "=f"(lo), "=f"(hi) : "l"(v));
}
__device__ __forceinline__ ull ffma2(ull a, ull b, ull c) {
    ull d; asm("fma.rn.f32x2 %0,%1,%2,%3;" : "=l"(d) : "l"(a), "l"(b), "l"(c)); return d;
}

// PASS 0: coef = softmax(bias); s0 += coef*u_hat
// PASS 1: v1=squash(s0); b1 = uh.v1 + 2*bias (store); s1 += softmax(b1)*u_hat
// PASS 2: v2=squash(s1); b2 = uh.v2 + b1 + bias;      s2 += softmax(b2)*u_hat
template <int PASS>
__global__ void __launch_bounds__(NTH, 2)
pass_kernel(const float* __restrict__ x,     // [256,1152,8]
            const float* __restrict__ W,     // [1152,10,16,8]
            const float* __restrict__ bias)  // [1152,10]
{
    extern __shared__ __align__(16) float sh[];
    float* ws  = sh;                  // [ii][c][e][d]  rows of 16 floats, 16B-aligned
    float* xs  = sh + WS_F;           // [j][lb] stride 33 (conflict-free both ways)
    float* exs = xs + XS_F;           // [2][32][11]

    const int tid = threadIdx.x;
    const int bb  = tid & 31;         // lane = batch within tile
    const int c   = tid >> 5;         // warp = capsule
    const int i0  = blockIdx.x * ITILE;
    const int b0  = blockIdx.y * B_TILE;
    const int b   = b0 + bb;

    // ---- Stage W tile: global [i][c][d][e] (float4 = d,e0..3) -> shared [ii][c][e][d]
    {
        const float4* Wg = (const float4*)(W + (size_t)i0 * NUM_CAPS * DIM_VEC * 8);
        #pragma unroll 2
        for (int k = tid; k < ITILE * NUM_CAPS * DIM_VEC * 2; k += NTH) {
            float4 w4 = Wg[k];                   // coalesced LDG.128
            int ii = k / (NUM_CAPS * DIM_VEC * 2);
            int r  = k - ii * (NUM_CAPS * DIM_VEC * 2);
            int cc = r >> 5;
            int d  = (r >> 1) & 15;
            int e0 = (r & 1) * 4;
            float* dst = ws + (((ii * NUM_CAPS + cc) * 8) + e0) * DIM_VEC + d;
            dst[0 * DIM_VEC] = w4.x;             // 2-way STS conflicts only
            dst[1 * DIM_VEC] = w4.y;
            dst[2 * DIM_VEC] = w4.z;
            dst[3 * DIM_VEC] = w4.w;
        }
    }
    // ---- Stage x tile transposed: xs[j][lb]
    for (int t = tid; t < B_TILE * ITILE * 8; t += NTH) {
        int lb = t >> 7;
        int j  = t & 127;
        xs[j * 33 + lb] = x[(size_t)(b0 + lb) * (IN_CAPS * 8) + i0 * 8 + j];
    }

    // ---- v = squash(s_prev) for this (b,c)
    ull vv2[8];
    if (PASS > 0) {
        const float4* sp = (const float4*)(g_sbuf[PASS - 1] + (b * NUM_CAPS + c) * DIM_VEC);
        float4 s4[4]; float sq = 0.f;
        #pragma unroll
        for (int q = 0; q < 4; q++) {
            s4[q] = sp[q];
            sq = fmaf(s4[q].x, s4[q].x, sq); sq = fmaf(s4[q].y, s4[q].y, sq);
            sq = fmaf(s4[q].z, s4[q].z, sq); sq = fmaf(s4[q].w, s4[q].w, sq);
        }
        float scale = sq / (1.f + sq) * rsqrtf(sq + EPS);
        #pragma unroll
        for (int q = 0; q < 4; q++) {
            vv2[2 * q]     = pack2(scale * s4[q].x, scale * s4[q].y);
            vv2[2 * q + 1] = pack2(scale * s4[q].z, scale * s4[q].w);
        }
    }
    __syncthreads();

    ull sacc2[8];
    #pragma unroll
    for (int p = 0; p < 8; p++) sacc2[p] = 0ull;

    #pragma unroll 1
    for (int ii = 0; ii < ITILE; ii++) {
        const int i = i0 + ii;
        const float bs = __ldg(&bias[i * NUM_CAPS + c]);               // warp-uniform
        float bprev;
        if (PASS == 2) bprev = g_blog[(i * NUM_CAPS + c) * BATCH + b]; // coalesced

        // u_hat[c,0..15] as 8 f32x2: 16 warp-uniform LDS.128 + 64 FFMA2
        ull uh2[8];
        #pragma unroll
        for (int p = 0; p < 8; p++) uh2[p] = 0ull;
        const ulonglong2* wp = (const ulonglong2*)(ws + ((ii * NUM_CAPS + c) * 8) * DIM_VEC);
        #pragma unroll
        for (int e = 0; e < 8; e++) {
            float xv = xs[(ii * 8 + e) * 33 + bb];                     // conflict-free
            ull x2 = pack2(xv, xv);
            #pragma unroll
            for (int q = 0; q < 4; q++) {
                ulonglong2 wv = wp[e * 4 + q];
                uh2[2 * q]     = ffma2(wv.x, x2, uh2[2 * q]);
                uh2[2 * q + 1] = ffma2(wv.y, x2, uh2[2 * q + 1]);
            }
        }

        float bnew;
        if (PASS == 0) {
            bnew = bs;
        } else {
            ull ag = 0ull;
            #pragma unroll
            for (int p = 0; p < 8; p++) ag = ffma2(uh2[p], vv2[p], ag);
            float alo, ahi; unpack2(ag, alo, ahi);
            float agr = alo + ahi;
            if (PASS == 1) {
                bnew = agr + 2.f * bs;
                g_blog[(i * NUM_CAPS + c) * BATCH + b] = bnew;         // coalesced STG
            } else {
                bnew = agr + bprev + bs;
            }
        }

        // softmax over 10 c's WITHOUT max-subtract (logits bounded) : 1 exp, 1 STS, 1 BAR
        float ex = __expf(bnew);
        const int pb = ii & 1;
        float* exr = exs + (pb * B_TILE + bb) * 11;
        exr[c] = ex;
        __syncthreads();
        float den = exr[0];
        #pragma unroll
        for (int k = 1; k < NUM_CAPS; k++) den += exr[k];
        float coef = __fdividef(ex, den);
        ull cf = pack2(coef, coef);
        #pragma unroll
        for (int p = 0; p < 8; p++) sacc2[p] = ffma2(cf, uh2[p], sacc2[p]);
    }

    // partial s[b,c,:] : 4 vectored global reductions (72 per address total)
    float* sp = g_sbuf[PASS] + (b * NUM_CAPS + c) * DIM_VEC;
    #pragma unroll
    for (int q = 0; q < 4; q++) {
        float a0, a1, a2, a3;
        unpack2(sacc2[2 * q],     a0, a1);
        unpack2(sacc2[2 * q + 1], a2, a3);
        asm volatile("red.global.add.v4.f32 [%0], {%1,%2,%3,%4};"
                     :: "l"(sp + 4 * q), "f"(a0), "f"(a1), "f"(a2), "f"(a3)
                     : "memory");
    }
}

// out = squash(s2); re-zero all scratch for graph-replay determinism
__global__ void final_kernel(float* __restrict__ out)
{
    int t = blockIdx.x * blockDim.x + threadIdx.x;
    if (t < BATCH * NUM_CAPS) {
        float4* sp = (float4*)(g_sbuf[2] + t * DIM_VEC);
        float4 s4[4]; float sq = 0.f;
        #pragma unroll
        for (int q = 0; q < 4; q++) {
            s4[q] = sp[q];
            sq = fmaf(s4[q].x, s4[q].x, sq); sq = fmaf(s4[q].y, s4[q].y, sq);
            sq = fmaf(s4[q].z, s4[q].z, sq); sq = fmaf(s4[q].w, s4[q].w, sq);
        }
        float scale = sq / (1.f + sq) * rsqrtf(sq + EPS);
        float4* dst = (float4*)(out + t * DIM_VEC);
        float4 z = make_float4(0.f, 0.f, 0.f, 0.f);
        #pragma unroll
        for (int q = 0; q < 4; q++) {
            float4 o; o.x = scale * s4[q].x; o.y = scale * s4[q].y;
                      o.z = scale * s4[q].z; o.w = scale * s4[q].w;
            dst[q] = o;
            sp[q] = z;
        }
    }
    if (t < BATCH * NUM_CAPS * DIM_VEC) {
        g_sbuf[0][t] = 0.f;
        g_sbuf[1][t] = 0.f;
    }
}

extern "C" void kernel_launch(void* const* d_in, const int* in_sizes, int n_in,
                              void* d_out, int out_size)
{
    const float* x = nullptr; const float* W = nullptr; const float* bias = nullptr;
    for (int k = 0; k < n_in; k++) {
        if (in_sizes[k] == BATCH * IN_CAPS * 8)                    x    = (const float*)d_in[k];
        else if (in_sizes[k] == IN_CAPS * NUM_CAPS * DIM_VEC * 8)  W    = (const float*)d_in[k];
        else if (in_sizes[k] == IN_CAPS * NUM_CAPS)                bias = (const float*)d_in[k];
    }
    float* out = (float*)d_out;

    cudaFuncSetAttribute(pass_kernel<0>, cudaFuncAttributeMaxDynamicSharedMemorySize, SMEM_BYTES);
    cudaFuncSetAttribute(pass_kernel<1>, cudaFuncAttributeMaxDynamicSharedMemorySize, SMEM_BYTES);
    cudaFuncSetAttribute(pass_kernel<2>, cudaFuncAttributeMaxDynamicSharedMemorySize, SMEM_BYTES);

    dim3 grd(NBLK_I, NBLK_B);
    pass_kernel<0><<<grd, NTH, SMEM_BYTES>>>(x, W, bias);
    pass_kernel<1><<<grd, NTH, SMEM_BYTES>>>(x, W, bias);
    pass_kernel<2><<<grd, NTH, SMEM_BYTES>>>(x, W, bias);
    final_kernel<<<(BATCH * NUM_CAPS * DIM_VEC + 255) / 256, 256>>>(out);
}